// round 17
// baseline (speedup 1.0000x reference)
#include <cuda_runtime.h>
#include <cuda_fp8.h>
#include <cuda_bf16.h>
#include <cstdint>

#define KDIM 2048
#define BLK  128
#define NKB  (KDIM / BLK)   // 16 K-blocks
#define M_MAX 8192
#define N_MAX 2048

// Scratch (allocation-free rule: __device__ globals)
__device__ __align__(16) uint8_t g_xq[(size_t)M_MAX * KDIM];    // 16 MB fp8 x
__device__ float g_xs[M_MAX * NKB];                              // per (m,kb) scales
__device__ __align__(16) uint8_t g_wq[(size_t)N_MAX * KDIM];    // 4 MB canonical fp8 w

// ---------------------------------------------------------------------------
// packed fp32x2 -> e4m3x2 convert (RN, satfinite — identical rounding to
// __nv_cvt_float_to_fp8). dst.lo = second operand, dst.hi = first operand.
// ---------------------------------------------------------------------------
#define CVT2_E4M3(dst16, vhi, vlo)                                             \
    asm("cvt.rn.satfinite.e4m3x2.f32 %0, %1, %2;"                              \
        : "=h"(dst16) : "f"(vhi), "f"(vlo))

__device__ __forceinline__ bool plaus_e4m3(float v) {
    if (!isfinite(v)) return false;
    float a = fabsf(v);
    if (a == 0.0f) return true;
    if (a < 0.001953125f || a > 448.0f) return false;
    __nv_fp8_storage_t q = __nv_cvt_float_to_fp8(v, __NV_SATFINITE, __NV_E4M3);
    float back = __half2float(__nv_cvt_fp8_to_halfraw(q, __NV_E4M3));
    return back == v;
}

// ---------------------------------------------------------------------------
// Fused prep kernel (unchanged from R14 — measured good):
//   blocks [0, cb):        weight canonicalization -> g_wq
//   blocks [cb, cb+qb):    blockwise x quantization (one warp per (m,kb))
// ---------------------------------------------------------------------------
__global__ void __launch_bounds__(256)
prep_kernel(const float* __restrict__ x, const void* __restrict__ w,
            int M, int wnelem) {
    const int cb  = wnelem / 4096;            // convert blocks (4096 elems each)
    const int tid = threadIdx.x;

    if ((int)blockIdx.x < cb) {
        bool ok32, okbf;
        {
            float v32 = reinterpret_cast<const float*>(w)[tid];
            ok32 = plaus_e4m3(v32);
            float vbf = __bfloat162float(
                reinterpret_cast<const __nv_bfloat16*>(w)[tid]);
            okbf = plaus_e4m3(vbf);
        }
        ok32 = __syncthreads_and(ok32);
        okbf = __syncthreads_and(okbf);
        const int fmt = ok32 ? 1 : (okbf ? 2 : 0);

        const int i = blockIdx.x * 4096 + tid * 16;
        uint32_t o[4];
        if (fmt == 1) {
            const float4* p = reinterpret_cast<const float4*>(
                reinterpret_cast<const float*>(w) + i);
#pragma unroll
            for (int j = 0; j < 4; j++) {
                float4 v = p[j];
                uint16_t lo, hi;
                CVT2_E4M3(lo, v.y, v.x);
                CVT2_E4M3(hi, v.w, v.z);
                o[j] = (uint32_t)lo | ((uint32_t)hi << 16);
            }
        } else if (fmt == 2) {
            const __nv_bfloat16* p = reinterpret_cast<const __nv_bfloat16*>(w) + i;
#pragma unroll
            for (int j = 0; j < 4; j++) {
                float v0 = __bfloat162float(p[4 * j + 0]);
                float v1 = __bfloat162float(p[4 * j + 1]);
                float v2 = __bfloat162float(p[4 * j + 2]);
                float v3 = __bfloat162float(p[4 * j + 3]);
                uint16_t lo, hi;
                CVT2_E4M3(lo, v1, v0);
                CVT2_E4M3(hi, v3, v2);
                o[j] = (uint32_t)lo | ((uint32_t)hi << 16);
            }
        } else {
            *reinterpret_cast<uint4*>(&o[0]) =
                reinterpret_cast<const uint4*>(
                    reinterpret_cast<const uint8_t*>(w) + i)[0];
        }
        *reinterpret_cast<uint4*>(g_wq + i) = *reinterpret_cast<uint4*>(o);
    } else {
        int gw   = ((blockIdx.x - cb) * 256 + tid) >> 5;
        int lane = tid & 31;
        int m    = gw >> 4;       // / NKB
        int kb   = gw & 15;
        if (m >= M) return;

        float4 v = reinterpret_cast<const float4*>(
            x + (size_t)m * KDIM + kb * BLK)[lane];
        float a = fmaxf(fmaxf(fabsf(v.x), fabsf(v.y)),
                        fmaxf(fabsf(v.z), fabsf(v.w)));
#pragma unroll
        for (int o2 = 16; o2 > 0; o2 >>= 1)
            a = fmaxf(a, __shfl_xor_sync(0xffffffffu, a, o2));

        a = fmaxf(a, 1e-12f);
        float s = __fdiv_rn(a, 448.0f);     // stored scale: bit-matches reference
        float r = __fdiv_rn(448.0f, a);     // fast per-element quant multiplier
        uint16_t p01, p23;
        CVT2_E4M3(p01, v.y * r, v.x * r);
        CVT2_E4M3(p23, v.w * r, v.z * r);
        uint32_t q = (uint32_t)p01 | ((uint32_t)p23 << 16);

        reinterpret_cast<uint32_t*>(g_xq + (size_t)m * KDIM + kb * BLK)[lane] = q;
        if (lane == 0) g_xs[m * NKB + kb] = s;
    }
}

// ---------------------------------------------------------------------------
// Kernel 2: fp8 mma.sync GEMM — telescoping-rescale, 3 CTAs/SM.
// 256 threads, warp grid 2x4, warp tile 32x32 (proven 16 LDSM : 32 MMA per
// kb), CTA tile 64x128, 2-stage cp.async ring (48KB). ONE accumulator set:
// MMA accumulates in place; between k-blocks acc *= sc_{kb-1}/sc_kb (4KB smem
// ratio table); final scale applied in the epilogue. __launch_bounds__(256,3)
// caps regs at 84 -> 3 CTAs = 24 warps/SM (6 per SMSP, 1.5x the R6 kernel).
// ---------------------------------------------------------------------------
__device__ __forceinline__ uint32_t su32(const void* p) {
    uint32_t a;
    asm("{ .reg .u64 t; cvta.to.shared.u64 t, %1; cvt.u32.u64 %0, t; }" : "=r"(a) : "l"(p));
    return a;
}

#define LDMX4(r0, r1, r2, r3, addr)                                            \
    asm volatile("ldmatrix.sync.aligned.m8n8.x4.shared.b16 {%0,%1,%2,%3}, [%4];" \
                 : "=r"(r0), "=r"(r1), "=r"(r2), "=r"(r3) : "r"(addr))

#define MMA_E4M3(d, a, b)                                                      \
    asm volatile("mma.sync.aligned.m16n8k32.row.col.f32.e4m3.e4m3.f32 "        \
                 "{%0,%1,%2,%3}, {%4,%5,%6,%7}, {%8,%9}, {%0,%1,%2,%3};"       \
                 : "+f"((d)[0]), "+f"((d)[1]), "+f"((d)[2]), "+f"((d)[3])      \
                 : "r"((a)[0]), "r"((a)[1]), "r"((a)[2]), "r"((a)[3]),         \
                   "r"((b)[0]), "r"((b)[1]))

#define CP16(saddr, gptr)                                                      \
    asm volatile("cp.async.cg.shared.global [%0], [%1], 16;" :: "r"(saddr), "l"(gptr))

// dynamic smem: 2 stages x (8K A + 16K B) + 4KB ratio table = 52KB
#define STG_BYTES 24576
#define B_OFF     8192
#define RT_OFF   (2 * STG_BYTES)             // 49152
#define SMEM_TOT (RT_OFF + 64 * NKB * 4)     // 53248

__global__ void __launch_bounds__(256, 3)
gemm_fp8_mma(const float* __restrict__ wsc, float* __restrict__ out, int M, int N) {
    extern __shared__ uint8_t smem[];
    float* rt_s = reinterpret_cast<float*>(smem + RT_OFF);

    const int tid  = threadIdx.x;
    const int lane = tid & 31;
    const int wid  = tid >> 5;
    const int wm   = wid >> 2;      // 0..1  (32-row warp tile)
    const int wn   = wid & 3;       // 0..3  (32-col warp tile)
    const int m0 = blockIdx.x * 64;
    const int n0 = blockIdx.y * 128;

    // per-row rescale table: rt[m][kb] = sc[m][kb-1]/sc[m][kb],
    // sc = xs[m,kb]*ws[nb,kb]  (validated telescoping, R11)
    {
        const float* xsg = g_xs + (size_t)m0 * NKB;
        const float* wsg = wsc + (n0 >> 7) * NKB;
        for (int i = tid; i < 64 * NKB; i += 256) {
            int m = i >> 4, kb = i & 15;
            float cur = xsg[m * NKB + kb] * wsg[kb];
            float prev = kb ? xsg[m * NKB + kb - 1] * wsg[kb - 1] : cur;
            rt_s[i] = __fdiv_rn(prev, cur);
        }
    }

    const uint32_t sa0 = su32(smem);

    // fragment source rows (validated mapping)
    const int a_row = wm * 32 + (lane & 7) + ((lane >> 3) & 1) * 8;
    const int a_k16 = ((lane >> 4) & 1) * 16;
    const int b_row = wn * 32 + (lane & 7) + ((lane >> 4) & 1) * 8;
    const int b_k16 = ((lane >> 3) & 1) * 16;

    // stage loaders:
    //   A tile 64x128B:  4 thr/row, 2 x 16B (cols c, c+64)
    //   B tile 128x128B: 2 thr/row, 4 x 16B (cols c+32i)
    const int la_row = tid >> 2, la_c = (tid & 3) * 16;
    const int lb_row = tid >> 1, lb_c = (tid & 1) * 16;
    const uint8_t* agp = g_xq + (size_t)(m0 + la_row) * KDIM + la_c;
    const uint8_t* bgp = g_wq + (size_t)(n0 + lb_row) * KDIM + lb_c;
    int a_st[2], b_st[4];
#pragma unroll
    for (int i = 0; i < 2; i++) {
        int off = la_row * 128 + la_c + i * 64;
        a_st[i] = off ^ ((off >> 3) & 0x70);
    }
#pragma unroll
    for (int i = 0; i < 4; i++) {
        int off = lb_row * 128 + lb_c + i * 32;
        b_st[i] = off ^ ((off >> 3) & 0x70);
    }

    // single accumulator set: 2 mf x 4 nf x 4 = 32 floats
    float acc[2][4][4];
#pragma unroll
    for (int i = 0; i < 2; i++)
#pragma unroll
        for (int j = 0; j < 4; j++)
#pragma unroll
            for (int c = 0; c < 4; c++) acc[i][j][c] = 0.0f;

#define LOAD_STAGE(kb, s)                                                      \
    do {                                                                       \
        uint32_t da = sa0 + (s) * STG_BYTES;                                   \
        uint32_t db = da + B_OFF;                                              \
        _Pragma("unroll")                                                      \
        for (int i = 0; i < 2; i++)                                            \
            CP16(da + a_st[i], agp + (kb) * BLK + i * 64);                     \
        _Pragma("unroll")                                                      \
        for (int i = 0; i < 4; i++)                                            \
            CP16(db + b_st[i], bgp + (kb) * BLK + i * 32);                     \
        asm volatile("cp.async.commit_group;");                                \
    } while (0)

// rescale acc by per-row ratio (kb > 0 only), then MMA-accumulate the k-block
#define COMPUTE_KB(kb, s)                                                      \
    do {                                                                       \
        if (kb) {                                                              \
            _Pragma("unroll")                                                  \
            for (int mf = 0; mf < 2; mf++) {                                   \
                int r0 = wm * 32 + mf * 16 + (lane >> 2);                      \
                float rlo = rt_s[r0 * NKB + (kb)];                             \
                float rhi = rt_s[(r0 + 8) * NKB + (kb)];                       \
                _Pragma("unroll")                                              \
                for (int nf = 0; nf < 4; nf++) {                               \
                    acc[mf][nf][0] *= rlo; acc[mf][nf][1] *= rlo;              \
                    acc[mf][nf][2] *= rhi; acc[mf][nf][3] *= rhi;              \
                }                                                              \
            }                                                                  \
        }                                                                      \
        const uint32_t ta = sa0 + (s) * STG_BYTES;                             \
        const uint32_t tb = ta + B_OFF;                                        \
        _Pragma("unroll")                                                      \
        for (int kc = 0; kc < 4; kc++) {                                       \
            uint32_t af[2][4];                                                 \
            _Pragma("unroll")                                                  \
            for (int mf = 0; mf < 2; mf++) {                                   \
                int off = (a_row + mf * 16) * 128 + kc * 32 + a_k16;           \
                int sw  = off ^ ((off >> 3) & 0x70);                           \
                LDMX4(af[mf][0], af[mf][1], af[mf][2], af[mf][3], ta + sw);    \
            }                                                                  \
            uint32_t bf[4][2];                                                 \
            _Pragma("unroll")                                                  \
            for (int nj = 0; nj < 2; nj++) {                                   \
                int off = (b_row + nj * 16) * 128 + kc * 32 + b_k16;           \
                int sw  = off ^ ((off >> 3) & 0x70);                           \
                uint32_t r0, r1, r2, r3;                                       \
                LDMX4(r0, r1, r2, r3, tb + sw);                                \
                bf[nj * 2][0] = r0; bf[nj * 2][1] = r1;                        \
                bf[nj * 2 + 1][0] = r2; bf[nj * 2 + 1][1] = r3;                \
            }                                                                  \
            _Pragma("unroll")                                                  \
            for (int mf = 0; mf < 2; mf++)                                     \
                _Pragma("unroll")                                              \
                for (int nf = 0; nf < 4; nf++)                                 \
                    MMA_E4M3(acc[mf][nf], af[mf], bf[nf]);                     \
        }                                                                      \
    } while (0)

    LOAD_STAGE(0, 0);

    // 2-stage ring: issue next load, wait for current, compute; trailing
    // barrier protects stage s against the kb+2 refill. First barrier also
    // publishes the rescale table.
    for (int kb = 0; kb < NKB; kb++) {
        const int s = kb & 1;
        if (kb + 1 < NKB) {
            LOAD_STAGE(kb + 1, s ^ 1);
            asm volatile("cp.async.wait_group 1;");
        } else {
            asm volatile("cp.async.wait_group 0;");
        }
        __syncthreads();
        COMPUTE_KB(kb, s);
        __syncthreads();
    }

    // epilogue: apply final scale sc[m][NKB-1] = xs[m][15]*ws[15] (L2-hot)
    {
        const float ws15 = wsc[(n0 >> 7) * NKB + (NKB - 1)];
#pragma unroll
        for (int mf = 0; mf < 2; mf++) {
            int rl = wm * 32 + mf * 16 + (lane >> 2);
            int r0 = m0 + rl;
            float flo = g_xs[(size_t)r0 * NKB + (NKB - 1)] * ws15;
            float fhi = g_xs[(size_t)(r0 + 8) * NKB + (NKB - 1)] * ws15;
#pragma unroll
            for (int nf = 0; nf < 4; nf++) {
                int c = n0 + wn * 32 + nf * 8 + (lane & 3) * 2;
                *reinterpret_cast<float2*>(out + (size_t)r0 * N + c) =
                    make_float2(acc[mf][nf][0] * flo, acc[mf][nf][1] * flo);
                *reinterpret_cast<float2*>(out + (size_t)(r0 + 8) * N + c) =
                    make_float2(acc[mf][nf][2] * fhi, acc[mf][nf][3] * fhi);
            }
        }
    }
}

// ---------------------------------------------------------------------------
extern "C" void kernel_launch(void* const* d_in, const int* in_sizes, int n_in,
                              void* d_out, int out_size) {
    const float* x  = (const float*)d_in[0];
    const void*  w  = d_in[1];                     // fp8 weight, representation detected
    const float* ws = (const float*)d_in[2];       // [N/128, K/128] fp32
    float* out = (float*)d_out;

    const int M = in_sizes[0] / KDIM;              // 8192
    const int N = in_sizes[1] / KDIM;              // 2048
    const int WN = in_sizes[1];                    // N*K elements

    // fused prep: weight convert blocks + x quant blocks in one launch
    const int cb = WN / 4096;                      // 1024
    const int qb = (M * NKB) / 8;                  // 16384 (8 warps per block)
    prep_kernel<<<cb + qb, 256>>>(x, w, M, WN);

    static int smem_set = 0;
    if (!smem_set) {
        cudaFuncSetAttribute(gemm_fp8_mma,
                             cudaFuncAttributeMaxDynamicSharedMemorySize, SMEM_TOT);
        smem_set = 1;
    }
    dim3 grid(M / 64, N / 128);
    gemm_fp8_mma<<<grid, 256, SMEM_TOT>>>(ws, out, M, N);
}